// round 2
// baseline (speedup 1.0000x reference)
#include <cuda_runtime.h>
#include <math.h>

#define T    512
#define H    2048
#define II   1024
#define E    64
#define KSEL 8

#define BM 32
#define BN 128
#define BK 32
#define PAD 4

// -------- device-global scratch (no allocations allowed) --------
__device__ int   g_cnt[E];
__device__ int   g_off[E];
__device__ int   g_tok[E * T];
__device__ float g_prob[E * T];
__device__ float g_act[(size_t)T * KSEL * II];   // 16 MB compact activation rows

// ======================= gating =======================
__global__ void gate_kernel(const float* __restrict__ x,
                            const float* __restrict__ Wgate)
{
    __shared__ float sx[H];
    __shared__ float slog[E];
    __shared__ int   s_ids[KSEL];
    __shared__ float s_p[KSEL];

    const int t   = blockIdx.x;
    const int tid = threadIdx.x;

    for (int i = tid; i < H; i += blockDim.x) sx[i] = x[(size_t)t * H + i];
    __syncthreads();

    const int w = tid >> 5, lane = tid & 31;
    // 8 warps x 8 experts each
    for (int j = 0; j < 8; j++) {
        const int e = w * 8 + j;
        const float* wr = Wgate + (size_t)e * H;
        float s = 0.f;
        for (int h = lane; h < H; h += 32) s += sx[h] * wr[h];
        #pragma unroll
        for (int o = 16; o > 0; o >>= 1) s += __shfl_xor_sync(0xffffffffu, s, o);
        if (lane == 0) slog[e] = s;
    }
    __syncthreads();

    if (tid == 0) {
        float vals[KSEL]; int ids[KSEL];
        for (int j = 0; j < KSEL; j++) {
            float best = -1e30f; int bi = 0;
            for (int e = 0; e < E; e++)
                if (slog[e] > best) { best = slog[e]; bi = e; }
            vals[j] = best; ids[j] = bi; slog[bi] = -1e30f;
        }
        const float m = vals[0];
        float sum = 0.f;
        for (int j = 0; j < KSEL; j++) { vals[j] = expf(vals[j] - m); sum += vals[j]; }
        const float inv = 1.f / sum;
        for (int j = 0; j < KSEL; j++) { s_ids[j] = ids[j]; s_p[j] = vals[j] * inv; }
    }
    __syncthreads();

    if (tid < KSEL) {
        const int e = s_ids[tid];
        const int pos = atomicAdd(&g_cnt[e], 1);
        g_tok[e * T + pos]  = t;
        g_prob[e * T + pos] = s_p[tid];
    }
}

__global__ void scan_kernel()
{
    if (threadIdx.x == 0) {
        int s = 0;
        for (int e = 0; e < E; e++) { g_off[e] = s; s += g_cnt[e]; }
    }
}

// ======================= gate/up GEMM + SwiGLU =======================
// C[m, n] over (tokens of expert e) x (I slice), K = H.
__global__ __launch_bounds__(256) void gateup_kernel(const float* __restrict__ x,
                                                     const float* __restrict__ Wg,
                                                     const float* __restrict__ Wu)
{
    const int e   = blockIdx.z;
    const int cnt = g_cnt[e];
    const int m0  = blockIdx.y * BM;
    if (m0 >= cnt) return;
    const int n0   = blockIdx.x * BN;
    const int base = g_off[e];

    __shared__ float As [BK][BM + PAD];
    __shared__ float Bgs[BK][BN + PAD];
    __shared__ float Bus[BK][BN + PAD];

    const int tid = threadIdx.x;
    const int lm  = tid >> 3;          // 0..31
    const int lk  = (tid & 7) << 2;    // 0,4,...,28

    const int tokm = min(m0 + lm, cnt - 1);
    const float* xrow = x + (size_t)g_tok[e * T + tokm] * H;
    const float* WgE  = Wg + ((size_t)e * II + n0) * H;
    const float* WuE  = Wu + ((size_t)e * II + n0) * H;

    const int tx = tid & 31;           // col group: n = tx*4 + c
    const int ty = tid >> 5;           // row group: m = ty*4 + r

    float cg[4][4] = {}, cu[4][4] = {};

    for (int k0 = 0; k0 < H; k0 += BK) {
        float4 av = *(const float4*)(xrow + k0 + lk);
        As[lk + 0][lm] = av.x; As[lk + 1][lm] = av.y;
        As[lk + 2][lm] = av.z; As[lk + 3][lm] = av.w;
        #pragma unroll
        for (int p = 0; p < 4; p++) {
            const int n = p * 32 + lm;
            float4 bv = *(const float4*)(WgE + (size_t)n * H + k0 + lk);
            Bgs[lk + 0][n] = bv.x; Bgs[lk + 1][n] = bv.y;
            Bgs[lk + 2][n] = bv.z; Bgs[lk + 3][n] = bv.w;
            float4 uv = *(const float4*)(WuE + (size_t)n * H + k0 + lk);
            Bus[lk + 0][n] = uv.x; Bus[lk + 1][n] = uv.y;
            Bus[lk + 2][n] = uv.z; Bus[lk + 3][n] = uv.w;
        }
        __syncthreads();
        #pragma unroll
        for (int kk = 0; kk < BK; kk++) {
            float4 a  = *(const float4*)&As [kk][ty * 4];
            float4 bg = *(const float4*)&Bgs[kk][tx * 4];
            float4 bu = *(const float4*)&Bus[kk][tx * 4];
            const float ar[4]  = {a.x,  a.y,  a.z,  a.w};
            const float bgr[4] = {bg.x, bg.y, bg.z, bg.w};
            const float bur[4] = {bu.x, bu.y, bu.z, bu.w};
            #pragma unroll
            for (int r = 0; r < 4; r++)
                #pragma unroll
                for (int c = 0; c < 4; c++) {
                    cg[r][c] += ar[r] * bgr[c];
                    cu[r][c] += ar[r] * bur[c];
                }
        }
        __syncthreads();
    }

    #pragma unroll
    for (int r = 0; r < 4; r++) {
        const int m = ty * 4 + r;
        if (m0 + m >= cnt) continue;
        const float p = g_prob[e * T + m0 + m];
        float* arow = g_act + (size_t)(base + m0 + m) * II + n0;
        #pragma unroll
        for (int c = 0; c < 4; c++) {
            const float hg = cg[r][c], hu = cu[r][c];
            arow[tx * 4 + c] = hg / (1.f + expf(-hg)) * hu * p;
        }
    }
}

// ======================= down GEMM + scatter-accumulate =======================
// out[t, n] += sum_k act[row, k] * Wd[e, n, k];  N over H, K = I.
__global__ __launch_bounds__(256) void down_kernel(const float* __restrict__ Wd,
                                                   float* __restrict__ out)
{
    const int e   = blockIdx.z;
    const int cnt = g_cnt[e];
    const int m0  = blockIdx.y * BM;
    if (m0 >= cnt) return;
    const int n0   = blockIdx.x * BN;
    const int base = g_off[e];

    __shared__ float As[BK][BM + PAD];
    __shared__ float Bs[BK][BN + PAD];

    const int tid = threadIdx.x;
    const int lm  = tid >> 3;
    const int lk  = (tid & 7) << 2;

    const int row = base + min(m0 + lm, cnt - 1);
    const float* arowg = g_act + (size_t)row * II;
    const float* WdE   = Wd + ((size_t)e * H + n0) * II;

    const int tx = tid & 31;
    const int ty = tid >> 5;

    float acc[4][4] = {};

    for (int k0 = 0; k0 < II; k0 += BK) {
        float4 av = *(const float4*)(arowg + k0 + lk);
        As[lk + 0][lm] = av.x; As[lk + 1][lm] = av.y;
        As[lk + 2][lm] = av.z; As[lk + 3][lm] = av.w;
        #pragma unroll
        for (int p = 0; p < 4; p++) {
            const int n = p * 32 + lm;
            float4 bv = *(const float4*)(WdE + (size_t)n * II + k0 + lk);
            Bs[lk + 0][n] = bv.x; Bs[lk + 1][n] = bv.y;
            Bs[lk + 2][n] = bv.z; Bs[lk + 3][n] = bv.w;
        }
        __syncthreads();
        #pragma unroll
        for (int kk = 0; kk < BK; kk++) {
            float4 a = *(const float4*)&As[kk][ty * 4];
            float4 b = *(const float4*)&Bs[kk][tx * 4];
            const float ar[4] = {a.x, a.y, a.z, a.w};
            const float br[4] = {b.x, b.y, b.z, b.w};
            #pragma unroll
            for (int r = 0; r < 4; r++)
                #pragma unroll
                for (int c = 0; c < 4; c++)
                    acc[r][c] += ar[r] * br[c];
        }
        __syncthreads();
    }

    #pragma unroll
    for (int r = 0; r < 4; r++) {
        const int m = ty * 4 + r;
        if (m0 + m >= cnt) continue;
        const int t = g_tok[e * T + m0 + m];
        float* orow = out + (size_t)t * H + n0;
        #pragma unroll
        for (int c = 0; c < 4; c++)
            atomicAdd(&orow[tx * 4 + c], acc[r][c]);
    }
}

// ======================= launch =======================
extern "C" void kernel_launch(void* const* d_in, const int* in_sizes, int n_in,
                              void* d_out, int out_size)
{
    const float* x     = (const float*)d_in[0];
    const float* Wg    = (const float*)d_in[1];
    const float* Wu    = (const float*)d_in[2];
    const float* Wd    = (const float*)d_in[3];
    const float* Wgate = (const float*)d_in[4];
    float* out = (float*)d_out;

    void* cnt_ptr = nullptr;
    cudaGetSymbolAddress(&cnt_ptr, g_cnt);
    cudaMemsetAsync(cnt_ptr, 0, E * sizeof(int));
    cudaMemsetAsync(d_out, 0, (size_t)T * H * sizeof(float));

    gate_kernel<<<T, 256>>>(x, Wgate);
    scan_kernel<<<1, 32>>>();

    dim3 g1(II / BN, T / BM, E);
    gateup_kernel<<<g1, 256>>>(x, Wg, Wu);

    dim3 g2(H / BN, T / BM, E);
    down_kernel<<<g2, 256>>>(Wd, out);
}

// round 3
// speedup vs baseline: 1.0001x; 1.0001x over previous
#include <cuda_runtime.h>
#include <math.h>

#define T    512
#define H    2048
#define II   1024
#define E    64
#define KSEL 8

#define BM 32
#define BN 128
#define BK 32
#define PAD 4

// -------- device-global scratch (no allocations allowed) --------
__device__ int   g_cnt[E];
__device__ int   g_off[E];
__device__ int   g_tok[E * T];
__device__ float g_prob[E * T];
__device__ float g_act[(size_t)T * KSEL * II];   // 16 MB compact activation rows

// ======================= gating =======================
__global__ void gate_kernel(const float* __restrict__ x,
                            const float* __restrict__ Wgate)
{
    __shared__ float sx[H];
    __shared__ float slog[E];
    __shared__ int   s_ids[KSEL];
    __shared__ float s_p[KSEL];

    const int t   = blockIdx.x;
    const int tid = threadIdx.x;

    for (int i = tid; i < H; i += blockDim.x) sx[i] = x[(size_t)t * H + i];
    __syncthreads();

    const int w = tid >> 5, lane = tid & 31;
    // 8 warps x 8 experts each
    for (int j = 0; j < 8; j++) {
        const int e = w * 8 + j;
        const float* wr = Wgate + (size_t)e * H;
        float s = 0.f;
        for (int h = lane; h < H; h += 32) s += sx[h] * wr[h];
        #pragma unroll
        for (int o = 16; o > 0; o >>= 1) s += __shfl_xor_sync(0xffffffffu, s, o);
        if (lane == 0) slog[e] = s;
    }
    __syncthreads();

    if (tid == 0) {
        float vals[KSEL]; int ids[KSEL];
        for (int j = 0; j < KSEL; j++) {
            float best = -1e30f; int bi = 0;
            for (int e = 0; e < E; e++)
                if (slog[e] > best) { best = slog[e]; bi = e; }
            vals[j] = best; ids[j] = bi; slog[bi] = -1e30f;
        }
        const float m = vals[0];
        float sum = 0.f;
        for (int j = 0; j < KSEL; j++) { vals[j] = expf(vals[j] - m); sum += vals[j]; }
        const float inv = 1.f / sum;
        for (int j = 0; j < KSEL; j++) { s_ids[j] = ids[j]; s_p[j] = vals[j] * inv; }
    }
    __syncthreads();

    if (tid < KSEL) {
        const int e = s_ids[tid];
        const int pos = atomicAdd(&g_cnt[e], 1);
        g_tok[e * T + pos]  = t;
        g_prob[e * T + pos] = s_p[tid];
    }
}

__global__ void scan_kernel()
{
    if (threadIdx.x == 0) {
        int s = 0;
        for (int e = 0; e < E; e++) { g_off[e] = s; s += g_cnt[e]; }
    }
}

// ======================= gate/up GEMM + SwiGLU =======================
// C[m, n] over (tokens of expert e) x (I slice), K = H.
__global__ __launch_bounds__(256) void gateup_kernel(const float* __restrict__ x,
                                                     const float* __restrict__ Wg,
                                                     const float* __restrict__ Wu)
{
    const int e   = blockIdx.z;
    const int cnt = g_cnt[e];
    const int m0  = blockIdx.y * BM;
    if (m0 >= cnt) return;
    const int n0   = blockIdx.x * BN;
    const int base = g_off[e];

    __shared__ float As [BK][BM + PAD];
    __shared__ float Bgs[BK][BN + PAD];
    __shared__ float Bus[BK][BN + PAD];

    const int tid = threadIdx.x;
    const int lm  = tid >> 3;          // 0..31
    const int lk  = (tid & 7) << 2;    // 0,4,...,28

    const int tokm = min(m0 + lm, cnt - 1);
    const float* xrow = x + (size_t)g_tok[e * T + tokm] * H;
    const float* WgE  = Wg + ((size_t)e * II + n0) * H;
    const float* WuE  = Wu + ((size_t)e * II + n0) * H;

    const int tx = tid & 31;           // col group: n = tx*4 + c
    const int ty = tid >> 5;           // row group: m = ty*4 + r

    float cg[4][4] = {}, cu[4][4] = {};

    for (int k0 = 0; k0 < H; k0 += BK) {
        float4 av = *(const float4*)(xrow + k0 + lk);
        As[lk + 0][lm] = av.x; As[lk + 1][lm] = av.y;
        As[lk + 2][lm] = av.z; As[lk + 3][lm] = av.w;
        #pragma unroll
        for (int p = 0; p < 4; p++) {
            const int n = p * 32 + lm;
            float4 bv = *(const float4*)(WgE + (size_t)n * H + k0 + lk);
            Bgs[lk + 0][n] = bv.x; Bgs[lk + 1][n] = bv.y;
            Bgs[lk + 2][n] = bv.z; Bgs[lk + 3][n] = bv.w;
            float4 uv = *(const float4*)(WuE + (size_t)n * H + k0 + lk);
            Bus[lk + 0][n] = uv.x; Bus[lk + 1][n] = uv.y;
            Bus[lk + 2][n] = uv.z; Bus[lk + 3][n] = uv.w;
        }
        __syncthreads();
        #pragma unroll
        for (int kk = 0; kk < BK; kk++) {
            float4 a  = *(const float4*)&As [kk][ty * 4];
            float4 bg = *(const float4*)&Bgs[kk][tx * 4];
            float4 bu = *(const float4*)&Bus[kk][tx * 4];
            const float ar[4]  = {a.x,  a.y,  a.z,  a.w};
            const float bgr[4] = {bg.x, bg.y, bg.z, bg.w};
            const float bur[4] = {bu.x, bu.y, bu.z, bu.w};
            #pragma unroll
            for (int r = 0; r < 4; r++)
                #pragma unroll
                for (int c = 0; c < 4; c++) {
                    cg[r][c] += ar[r] * bgr[c];
                    cu[r][c] += ar[r] * bur[c];
                }
        }
        __syncthreads();
    }

    #pragma unroll
    for (int r = 0; r < 4; r++) {
        const int m = ty * 4 + r;
        if (m0 + m >= cnt) continue;
        const float p = g_prob[e * T + m0 + m];
        float* arow = g_act + (size_t)(base + m0 + m) * II + n0;
        #pragma unroll
        for (int c = 0; c < 4; c++) {
            const float hg = cg[r][c], hu = cu[r][c];
            arow[tx * 4 + c] = hg / (1.f + expf(-hg)) * hu * p;
        }
    }
}

// ======================= down GEMM + scatter-accumulate =======================
// out[t, n] += sum_k act[row, k] * Wd[e, n, k];  N over H, K = I.
__global__ __launch_bounds__(256) void down_kernel(const float* __restrict__ Wd,
                                                   float* __restrict__ out)
{
    const int e   = blockIdx.z;
    const int cnt = g_cnt[e];
    const int m0  = blockIdx.y * BM;
    if (m0 >= cnt) return;
    const int n0   = blockIdx.x * BN;
    const int base = g_off[e];

    __shared__ float As[BK][BM + PAD];
    __shared__ float Bs[BK][BN + PAD];

    const int tid = threadIdx.x;
    const int lm  = tid >> 3;
    const int lk  = (tid & 7) << 2;

    const int row = base + min(m0 + lm, cnt - 1);
    const float* arowg = g_act + (size_t)row * II;
    const float* WdE   = Wd + ((size_t)e * H + n0) * II;

    const int tx = tid & 31;
    const int ty = tid >> 5;

    float acc[4][4] = {};

    for (int k0 = 0; k0 < II; k0 += BK) {
        float4 av = *(const float4*)(arowg + k0 + lk);
        As[lk + 0][lm] = av.x; As[lk + 1][lm] = av.y;
        As[lk + 2][lm] = av.z; As[lk + 3][lm] = av.w;
        #pragma unroll
        for (int p = 0; p < 4; p++) {
            const int n = p * 32 + lm;
            float4 bv = *(const float4*)(WdE + (size_t)n * II + k0 + lk);
            Bs[lk + 0][n] = bv.x; Bs[lk + 1][n] = bv.y;
            Bs[lk + 2][n] = bv.z; Bs[lk + 3][n] = bv.w;
        }
        __syncthreads();
        #pragma unroll
        for (int kk = 0; kk < BK; kk++) {
            float4 a = *(const float4*)&As[kk][ty * 4];
            float4 b = *(const float4*)&Bs[kk][tx * 4];
            const float ar[4] = {a.x, a.y, a.z, a.w};
            const float br[4] = {b.x, b.y, b.z, b.w};
            #pragma unroll
            for (int r = 0; r < 4; r++)
                #pragma unroll
                for (int c = 0; c < 4; c++)
                    acc[r][c] += ar[r] * br[c];
        }
        __syncthreads();
    }

    #pragma unroll
    for (int r = 0; r < 4; r++) {
        const int m = ty * 4 + r;
        if (m0 + m >= cnt) continue;
        const int t = g_tok[e * T + m0 + m];
        float* orow = out + (size_t)t * H + n0;
        #pragma unroll
        for (int c = 0; c < 4; c++)
            atomicAdd(&orow[tx * 4 + c], acc[r][c]);
    }
}

// ======================= launch =======================
extern "C" void kernel_launch(void* const* d_in, const int* in_sizes, int n_in,
                              void* d_out, int out_size)
{
    const float* x     = (const float*)d_in[0];
    const float* Wg    = (const float*)d_in[1];
    const float* Wu    = (const float*)d_in[2];
    const float* Wd    = (const float*)d_in[3];
    const float* Wgate = (const float*)d_in[4];
    float* out = (float*)d_out;

    void* cnt_ptr = nullptr;
    cudaGetSymbolAddress(&cnt_ptr, g_cnt);
    cudaMemsetAsync(cnt_ptr, 0, E * sizeof(int));
    cudaMemsetAsync(d_out, 0, (size_t)T * H * sizeof(float));

    gate_kernel<<<T, 256>>>(x, Wgate);
    scan_kernel<<<1, 32>>>();

    dim3 g1(II / BN, T / BM, E);
    gateup_kernel<<<g1, 256>>>(x, Wg, Wu);

    dim3 g2(H / BN, T / BM, E);
    down_kernel<<<g2, 256>>>(Wd, out);
}